// round 3
// baseline (speedup 1.0000x reference)
#include <cuda_runtime.h>

// Problem constants: B=16, S=1024, D=256, H=16, DK=16
#define NB 16
#define NS 1024
#define ND 256
#define NH 16
#define NDK 16

// Scratch for projected q,k,v: [B, S, 256] row-major (head h occupies cols h*16..h*16+15)
__device__ float g_q[NB * NS * ND];
__device__ float g_k[NB * NS * ND];
__device__ float g_v[NB * NS * ND];

// ---------------------------------------------------------------------------
// Packed dual-fp32 helpers (Blackwell f32x2).
// ---------------------------------------------------------------------------
typedef unsigned long long ull;

static __device__ __forceinline__ ull pack2(float lo, float hi) {
    ull r;
    asm("mov.b64 %0, {%1, %2};" : "=l"(r) : "f"(lo), "f"(hi));
    return r;
}
static __device__ __forceinline__ void unpack2(ull p, float& lo, float& hi) {
    asm("mov.b64 {%0, %1}, %2;" : "=f"(lo), "=f"(hi) : "l"(p));
}
static __device__ __forceinline__ ull fma2(ull a, ull b, ull c) {
    ull d;
    asm("fma.rn.f32x2 %0, %1, %2, %3;" : "=l"(d) : "l"(a), "l"(b), "l"(c));
    return d;
}
static __device__ __forceinline__ ull add2(ull a, ull b) {
    ull d;
    asm("add.rn.f32x2 %0, %1, %2;" : "=l"(d) : "l"(a), "l"(b));
    return d;
}
static __device__ __forceinline__ ull d2ll(double d) {
    return __double_as_longlong(d);
}

// Fast exp on the fma/alu pipes (no MUFU). x in ~[-12, 12], rel err ~2e-6.
// exp(x) = 2^(x*log2e): magic-number round, deg-5 Taylor for 2^f, exponent inject.
static __device__ __forceinline__ float fast_exp(float t /* = x*log2e already */) {
    float mm = t + 12582912.0f;             // round-to-nearest int (magic 2^23+2^22)
    int   ik = __float_as_int(mm);
    float n  = mm - 12582912.0f;
    float f  = t - n;                        // f in [-0.5, 0.5]
    float p  =             1.33335581464e-3f;
    p = fmaf(p, f, 9.61812910763e-3f);
    p = fmaf(p, f, 5.55041086648e-2f);
    p = fmaf(p, f, 2.40226506959e-1f);
    p = fmaf(p, f, 6.93147180560e-1f);
    p = fmaf(p, f, 1.0f);
    return __int_as_float(__float_as_int(p) + ((ik - 0x4B400000) << 23));
}

// ---------------------------------------------------------------------------
// Projection GEMM: C[16384,256] = X[16384,256] @ W[256,256] (+bias)
// ---------------------------------------------------------------------------
__global__ __launch_bounds__(256, 2) void proj_kernel(
    const float* __restrict__ Qin, const float* __restrict__ Kin, const float* __restrict__ Vin,
    const float* __restrict__ Wq, const float* __restrict__ bq,
    const float* __restrict__ Wk, const float* __restrict__ Wv, const float* __restrict__ bv)
{
    __shared__ float As[128][17];
    __shared__ float Bs[16][128];

    const int z = blockIdx.z;
    const float* X    = (z == 0) ? Qin : ((z == 1) ? Kin : Vin);
    const float* W    = (z == 0) ? Wq  : ((z == 1) ? Wk  : Wv);
    const float* bias = (z == 0) ? bq  : ((z == 2) ? bv  : (const float*)0);
    float* C          = (z == 0) ? g_q : ((z == 1) ? g_k : g_v);

    const int m0 = blockIdx.y * 128;
    const int n0 = blockIdx.x * 128;
    const int tid = threadIdx.x;
    const int tx = tid & 15;
    const int ty = tid >> 4;

    ull accp[8][4];
#pragma unroll
    for (int i = 0; i < 8; i++)
#pragma unroll
        for (int j = 0; j < 4; j++) accp[i][j] = 0ULL;

    for (int kk = 0; kk < 256; kk += 16) {
#pragma unroll
        for (int i = 0; i < 8; i++) {
            int r = (tid >> 4) + i * 16;
            int c = tid & 15;
            As[r][c] = X[(size_t)(m0 + r) * 256 + kk + c];
        }
#pragma unroll
        for (int i = 0; i < 8; i++) {
            int kr = (tid >> 7) + i * 2;
            int n  = tid & 127;
            Bs[kr][n] = W[(size_t)(kk + kr) * 256 + n0 + n];
        }
        __syncthreads();

#pragma unroll
        for (int k = 0; k < 16; k++) {
            const double2* brow = (const double2*)&Bs[k][tx * 8];
            double2 b0 = brow[0], b1 = brow[1];
            ull bp[4] = { d2ll(b0.x), d2ll(b0.y), d2ll(b1.x), d2ll(b1.y) };
#pragma unroll
            for (int i = 0; i < 8; i++) {
                float a = As[ty * 8 + i][k];
                ull a2 = pack2(a, a);
#pragma unroll
                for (int j = 0; j < 4; j++)
                    accp[i][j] = fma2(a2, bp[j], accp[i][j]);
            }
        }
        __syncthreads();
    }

    float bj[8];
#pragma unroll
    for (int j = 0; j < 8; j++)
        bj[j] = bias ? bias[n0 + tx * 8 + j] : 0.f;

#pragma unroll
    for (int i = 0; i < 8; i++) {
        int m = m0 + ty * 8 + i;
        float v[8];
#pragma unroll
        for (int j = 0; j < 4; j++) unpack2(accp[i][j], v[2 * j], v[2 * j + 1]);
        float4 o0, o1;
        o0.x = v[0] + bj[0]; o0.y = v[1] + bj[1];
        o0.z = v[2] + bj[2]; o0.w = v[3] + bj[3];
        o1.x = v[4] + bj[4]; o1.y = v[5] + bj[5];
        o1.z = v[6] + bj[6]; o1.w = v[7] + bj[7];
        *(float4*)&C[(size_t)m * 256 + n0 + tx * 8]     = o0;
        *(float4*)&C[(size_t)m * 256 + n0 + tx * 8 + 4] = o1;
    }
}

// ---------------------------------------------------------------------------
// Fused attention: one block per (b, h, 32-query tile). 512 threads (16 warps).
// Phase 1: warp = 8 rows (g=w&3) x 256 columns (cq=w>>2); q in regs (64 pairs),
//          scores via f32x2 dots, exp via fast_exp (no MUFU), -> sc + rowsums.
// Phase 3: warp = 4 rows x 512-column half; context via f32x2; normalized
//          attn_w store folded into the score re-read.
// ---------------------------------------------------------------------------
#define SC_OFF    0         // 32768 floats
#define KV_OFF    32768     // 20480
#define QS_OFF    53248     // 512
#define MSK_OFF   53760     // 1024
#define RSUM_OFF  54784     // 32
#define RSP_OFF   54816     // 128
#define CPART_OFF 54944     // 1024
#define ATTN_SMEM_FLOATS 55968
#define ATTN_SMEM_BYTES (ATTN_SMEM_FLOATS * 4)

__global__ __launch_bounds__(512, 1) void attn_kernel(
    const int* __restrict__ maskg, float* __restrict__ outg, float* __restrict__ attnw)
{
    extern __shared__ float sm[];
    float* sc    = sm + SC_OFF;
    float* kv    = sm + KV_OFF;
    float* qs    = sm + QS_OFF;
    float* msk   = sm + MSK_OFF;
    float* rsum  = sm + RSUM_OFF;
    float* rsp   = sm + RSP_OFF;
    float* cpart = sm + CPART_OFF;

    const int qt = blockIdx.x, h = blockIdx.y, b = blockIdx.z;
    const int tid  = threadIdx.x;
    const int lane = tid & 31;
    const int w    = tid >> 5;        // 0..15
    const int q0   = qt * 32;

    // --- stage q tile (32x16), mask (1024), K head tile (1024x16) ---
    {
        int r = tid >> 4, d = tid & 15;
        qs[tid] = g_q[(size_t)(b * NS + q0 + r) * ND + h * NDK + d];
    }
    msk[tid]       = (float)maskg[b * NS + tid];
    msk[tid + 512] = (float)maskg[b * NS + tid + 512];
    {
        const float* kbase = g_k + (size_t)b * NS * ND + h * NDK;
#pragma unroll
        for (int i = 0; i < 8; i++) {
            int idx = tid + i * 512;
            int j = idx >> 2, c = idx & 3;
            float4 t = *(const float4*)(kbase + (size_t)j * ND + c * 4);
            *(float4*)&kv[j * 20 + c * 4] = t;
        }
    }
    __syncthreads();

    // === Phase 1: scores. Warp mapping: g = w&3 (8 rows), cq = w>>2 (256 cols)
    {
        const int g  = w & 3;
        const int cq = w >> 2;

        // q rows -> packed register pairs over d: qp[r][c]
        ull qp[8][8];
#pragma unroll
        for (int r = 0; r < 8; r++) {
            const double2* qrow = (const double2*)&qs[(g * 8 + r) * 16];
#pragma unroll
            for (int c = 0; c < 4; c++) {
                double2 t = qrow[c];
                qp[r][2 * c]     = d2ll(t.x);
                qp[r][2 * c + 1] = d2ll(t.y);
            }
        }

        float rs[8];
#pragma unroll
        for (int r = 0; r < 8; r++) rs[r] = 0.f;

        // scale folded into log2 domain: t = s * (log2(e)/4)
        const float C_L2E4 = 0.36067376022224085f;

#pragma unroll 1
        for (int it = 0; it < 8; it++) {
            const int j = cq * 256 + it * 32 + lane;
            const double2* krow = (const double2*)&kv[j * 20];
            ull kp[8];
#pragma unroll
            for (int c = 0; c < 4; c++) {
                double2 t = krow[c];
                kp[2 * c]     = d2ll(t.x);
                kp[2 * c + 1] = d2ll(t.y);
            }
            const float m = msk[j];
            float sv[8];
#pragma unroll
            for (int r = 0; r < 8; r++) {
                ull s2 = 0ULL;
#pragma unroll
                for (int c = 0; c < 8; c++) s2 = fma2(qp[r][c], kp[c], s2);
                float slo, shi;
                unpack2(s2, slo, shi);
                sv[r] = slo + shi;
            }
#pragma unroll
            for (int r = 0; r < 8; r++) {
                float e = fast_exp(sv[r] * C_L2E4) * m;
                sc[(g * 8 + r) * 1024 + j] = e;
                rs[r] += e;
            }
        }

        // lane reduction
#pragma unroll
        for (int o = 16; o > 0; o >>= 1)
#pragma unroll
            for (int r = 0; r < 8; r++)
                rs[r] += __shfl_xor_sync(0xffffffffu, rs[r], o);
        if (lane == 0) {
#pragma unroll
            for (int r = 0; r < 8; r++) rsp[w * 8 + r] = rs[r];
        }
    }
    __syncthreads();
    if (tid < 32) {
        int g2 = tid >> 3, rr = tid & 7;
        float s = rsp[g2 * 8 + rr] + rsp[(g2 + 4) * 8 + rr]
                + rsp[(g2 + 8) * 8 + rr] + rsp[(g2 + 12) * 8 + rr];
        rsum[tid] = 1.0f / (s + 1e-8f);
    }
    __syncthreads();

    // --- stage V over kv (K no longer needed) ---
    {
        const float* vbase = g_v + (size_t)b * NS * ND + h * NDK;
#pragma unroll
        for (int i = 0; i < 8; i++) {
            int idx = tid + i * 512;
            int j = idx >> 2, c = idx & 3;
            float4 t = *(const float4*)(vbase + (size_t)j * ND + c * 4);
            *(float4*)&kv[j * 20 + c * 4] = t;
        }
    }
    __syncthreads();

    // === Phase 3: context = sc @ v; attn_w store folded in.
    // Warp mapping: rg = (w&7)*4 rows, half = w>>3.
    {
        const int rg   = (w & 7) * 4;
        const int half = w >> 3;

        float inv[4];
#pragma unroll
        for (int r = 0; r < 4; r++) inv[r] = rsum[rg + r];

        float* aw = attnw + ((size_t)(b * NH + h) * NS + q0) * NS;

        ull accp[4][8];
#pragma unroll
        for (int r = 0; r < 4; r++)
#pragma unroll
            for (int c = 0; c < 8; c++) accp[r][c] = 0ULL;

#pragma unroll 1
        for (int it = 0; it < 16; it++) {
            const int j = half * 512 + it * 32 + lane;
            const double2* vrow = (const double2*)&kv[j * 20];
            ull vp[8];
#pragma unroll
            for (int c = 0; c < 4; c++) {
                double2 t = vrow[c];
                vp[2 * c]     = d2ll(t.x);
                vp[2 * c + 1] = d2ll(t.y);
            }
#pragma unroll
            for (int r = 0; r < 4; r++) {
                float e = sc[(rg + r) * 1024 + j];
                aw[(size_t)(rg + r) * NS + j] = e * inv[r];
                ull e2 = pack2(e, e);
#pragma unroll
                for (int c = 0; c < 8; c++)
                    accp[r][c] = fma2(e2, vp[c], accp[r][c]);
            }
        }

#pragma unroll
        for (int o = 16; o > 0; o >>= 1)
#pragma unroll
            for (int r = 0; r < 4; r++)
#pragma unroll
                for (int c = 0; c < 8; c++)
                    accp[r][c] = add2(accp[r][c], __shfl_xor_sync(0xffffffffu, accp[r][c], o));

        if (lane == 0) {
#pragma unroll
            for (int r = 0; r < 4; r++)
#pragma unroll
                for (int c = 0; c < 8; c++) {
                    float lo, hi;
                    unpack2(accp[r][c], lo, hi);
                    cpart[w * 64 + r * 16 + 2 * c]     = lo;
                    cpart[w * 64 + r * 16 + 2 * c + 1] = hi;
                }
        }
    }
    __syncthreads();

    // combine the two column-half partials, normalize, write output
    {
        int r = tid >> 4, d = tid & 15;
        int wg = r >> 2, rr = r & 3;
        float v = cpart[wg * 64 + rr * 16 + d] + cpart[(wg + 8) * 64 + rr * 16 + d];
        v *= rsum[r];
        outg[(size_t)(b * NS + q0 + r) * ND + h * NDK + d] = v;
    }
}

// ---------------------------------------------------------------------------
extern "C" void kernel_launch(void* const* d_in, const int* in_sizes, int n_in,
                              void* d_out, int out_size)
{
    const float* Qin  = (const float*)d_in[0];
    const float* Kin  = (const float*)d_in[1];
    const float* Vin  = (const float*)d_in[2];
    const int*   mask = (const int*)d_in[3];
    const float* Wq   = (const float*)d_in[4];
    const float* bq   = (const float*)d_in[5];
    const float* Wk   = (const float*)d_in[6];
    const float* Wv   = (const float*)d_in[7];
    const float* bv   = (const float*)d_in[8];

    float* out   = (float*)d_out;
    float* attnw = out + (size_t)NB * NS * ND;

    dim3 pg(2, 128, 3);
    proj_kernel<<<pg, 256>>>(Qin, Kin, Vin, Wq, bq, Wk, Wv, bv);

    cudaFuncSetAttribute(attn_kernel, cudaFuncAttributeMaxDynamicSharedMemorySize,
                         ATTN_SMEM_BYTES);
    dim3 ag(NS / 32, NH, NB);
    attn_kernel<<<ag, 512, ATTN_SMEM_BYTES>>>(mask, out, attnw);
}

// round 4
// speedup vs baseline: 1.4704x; 1.4704x over previous
#include <cuda_runtime.h>

// Problem constants: B=16, S=1024, D=256, H=16, DK=16
#define NB 16
#define NS 1024
#define ND 256
#define NH 16
#define NDK 16

// Scratch for projected q,k,v: [B, S, 256] row-major (head h occupies cols h*16..h*16+15)
__device__ float g_q[NB * NS * ND];
__device__ float g_k[NB * NS * ND];
__device__ float g_v[NB * NS * ND];

// ---------------------------------------------------------------------------
// Packed dual-fp32 helpers (Blackwell f32x2).
// ---------------------------------------------------------------------------
typedef unsigned long long ull;

static __device__ __forceinline__ ull pack2(float lo, float hi) {
    ull r;
    asm("mov.b64 %0, {%1, %2};" : "=l"(r) : "f"(lo), "f"(hi));
    return r;
}
static __device__ __forceinline__ void unpack2(ull p, float& lo, float& hi) {
    asm("mov.b64 {%0, %1}, %2;" : "=f"(lo), "=f"(hi) : "l"(p));
}
static __device__ __forceinline__ ull fma2(ull a, ull b, ull c) {
    ull d;
    asm("fma.rn.f32x2 %0, %1, %2, %3;" : "=l"(d) : "l"(a), "l"(b), "l"(c));
    return d;
}
static __device__ __forceinline__ ull add2(ull a, ull b) {
    ull d;
    asm("add.rn.f32x2 %0, %1, %2;" : "=l"(d) : "l"(a), "l"(b));
    return d;
}
static __device__ __forceinline__ ull d2ll(double d) {
    return __double_as_longlong(d);
}

// Fast exp on the fma/alu pipes (no MUFU). Input is already x*log2(e).
// Magic-number round + deg-5 poly for 2^f + exponent injection. rel err ~2e-6.
static __device__ __forceinline__ float fast_exp(float t) {
    float mm = t + 12582912.0f;             // round-to-nearest (magic 2^23+2^22)
    int   ik = __float_as_int(mm);
    float n  = mm - 12582912.0f;
    float f  = t - n;                        // f in [-0.5, 0.5]
    float p  =             1.33335581464e-3f;
    p = fmaf(p, f, 9.61812910763e-3f);
    p = fmaf(p, f, 5.55041086648e-2f);
    p = fmaf(p, f, 2.40226506959e-1f);
    p = fmaf(p, f, 6.93147180560e-1f);
    p = fmaf(p, f, 1.0f);
    return __int_as_float(__float_as_int(p) + ((ik - 0x4B400000) << 23));
}

// ---------------------------------------------------------------------------
// Projection GEMM: C[16384,256] = X[16384,256] @ W[256,256] (+bias)
// ---------------------------------------------------------------------------
__global__ __launch_bounds__(256, 2) void proj_kernel(
    const float* __restrict__ Qin, const float* __restrict__ Kin, const float* __restrict__ Vin,
    const float* __restrict__ Wq, const float* __restrict__ bq,
    const float* __restrict__ Wk, const float* __restrict__ Wv, const float* __restrict__ bv)
{
    __shared__ float As[128][17];
    __shared__ float Bs[16][128];

    const int z = blockIdx.z;
    const float* X    = (z == 0) ? Qin : ((z == 1) ? Kin : Vin);
    const float* W    = (z == 0) ? Wq  : ((z == 1) ? Wk  : Wv);
    const float* bias = (z == 0) ? bq  : ((z == 2) ? bv  : (const float*)0);
    float* C          = (z == 0) ? g_q : ((z == 1) ? g_k : g_v);

    const int m0 = blockIdx.y * 128;
    const int n0 = blockIdx.x * 128;
    const int tid = threadIdx.x;
    const int tx = tid & 15;
    const int ty = tid >> 4;

    ull accp[8][4];
#pragma unroll
    for (int i = 0; i < 8; i++)
#pragma unroll
        for (int j = 0; j < 4; j++) accp[i][j] = 0ULL;

    for (int kk = 0; kk < 256; kk += 16) {
#pragma unroll
        for (int i = 0; i < 8; i++) {
            int r = (tid >> 4) + i * 16;
            int c = tid & 15;
            As[r][c] = X[(size_t)(m0 + r) * 256 + kk + c];
        }
#pragma unroll
        for (int i = 0; i < 8; i++) {
            int kr = (tid >> 7) + i * 2;
            int n  = tid & 127;
            Bs[kr][n] = W[(size_t)(kk + kr) * 256 + n0 + n];
        }
        __syncthreads();

#pragma unroll
        for (int k = 0; k < 16; k++) {
            const double2* brow = (const double2*)&Bs[k][tx * 8];
            double2 b0 = brow[0], b1 = brow[1];
            ull bp[4] = { d2ll(b0.x), d2ll(b0.y), d2ll(b1.x), d2ll(b1.y) };
#pragma unroll
            for (int i = 0; i < 8; i++) {
                float a = As[ty * 8 + i][k];
                ull a2 = pack2(a, a);
#pragma unroll
                for (int j = 0; j < 4; j++)
                    accp[i][j] = fma2(a2, bp[j], accp[i][j]);
            }
        }
        __syncthreads();
    }

    float bj[8];
#pragma unroll
    for (int j = 0; j < 8; j++)
        bj[j] = bias ? bias[n0 + tx * 8 + j] : 0.f;

#pragma unroll
    for (int i = 0; i < 8; i++) {
        int m = m0 + ty * 8 + i;
        float v[8];
#pragma unroll
        for (int j = 0; j < 4; j++) unpack2(accp[i][j], v[2 * j], v[2 * j + 1]);
        float4 o0, o1;
        o0.x = v[0] + bj[0]; o0.y = v[1] + bj[1];
        o0.z = v[2] + bj[2]; o0.w = v[3] + bj[3];
        o1.x = v[4] + bj[4]; o1.y = v[5] + bj[5];
        o1.z = v[6] + bj[6]; o1.w = v[7] + bj[7];
        *(float4*)&C[(size_t)m * 256 + n0 + tx * 8]     = o0;
        *(float4*)&C[(size_t)m * 256 + n0 + tx * 8 + 4] = o1;
    }
}

// ---------------------------------------------------------------------------
// Fused attention: one block per (b, h, 32-query tile). 512 threads (16 warps).
// ROUND-2 STRUCTURE (known 127-reg, no spills). Warp w: rows rg=(w&7)*4,
// column half w>>3. Only deltas vs round 2: fast_exp (no MUFU) and __stcs
// streaming stores for attn_w.
// ---------------------------------------------------------------------------
#define SC_OFF    0         // 32768 floats
#define KV_OFF    32768     // 20480
#define QS_OFF    53248     // 512
#define MSK_OFF   53760     // 1024
#define RSUM_OFF  54784     // 32
#define RSP_OFF   54816     // 64
#define CPART_OFF 54880     // 1024
#define ATTN_SMEM_FLOATS 55904
#define ATTN_SMEM_BYTES (ATTN_SMEM_FLOATS * 4)

__global__ __launch_bounds__(512, 1) void attn_kernel(
    const int* __restrict__ maskg, float* __restrict__ outg, float* __restrict__ attnw)
{
    extern __shared__ float sm[];
    float* sc    = sm + SC_OFF;
    float* kv    = sm + KV_OFF;
    float* qs    = sm + QS_OFF;
    float* msk   = sm + MSK_OFF;
    float* rsum  = sm + RSUM_OFF;
    float* rsp   = sm + RSP_OFF;
    float* cpart = sm + CPART_OFF;

    const int qt = blockIdx.x, h = blockIdx.y, b = blockIdx.z;
    const int tid  = threadIdx.x;
    const int lane = tid & 31;
    const int w    = tid >> 5;        // 0..15
    const int rg   = (w & 7) * 4;     // row group (4 rows)
    const int half = w >> 3;          // column half
    const int q0   = qt * 32;

    // --- stage q tile (32x16), mask (1024), K head tile (1024x16) ---
    {
        int r = tid >> 4, d = tid & 15;
        qs[tid] = g_q[(size_t)(b * NS + q0 + r) * ND + h * NDK + d];
    }
    msk[tid]       = (float)maskg[b * NS + tid];
    msk[tid + 512] = (float)maskg[b * NS + tid + 512];
    {
        const float* kbase = g_k + (size_t)b * NS * ND + h * NDK;
#pragma unroll
        for (int i = 0; i < 8; i++) {
            int idx = tid + i * 512;
            int j = idx >> 2, c = idx & 3;
            float4 t = *(const float4*)(kbase + (size_t)j * ND + c * 4);
            *(float4*)&kv[j * 20 + c * 4] = t;
        }
    }
    __syncthreads();

    // q rows -> packed register pairs over d: qp[r][c] = (q[2c], q[2c+1])
    ull qp[4][8];
#pragma unroll
    for (int r = 0; r < 4; r++) {
        const double2* qrow = (const double2*)&qs[(rg + r) * 16];
#pragma unroll
        for (int c = 0; c < 4; c++) {
            double2 t = qrow[c];
            qp[r][2 * c]     = d2ll(t.x);
            qp[r][2 * c + 1] = d2ll(t.y);
        }
    }

    // --- Phase 1: scores (dual-fp32 dot, fast_exp on fma/alu pipes) ---
    const float C_L2E4 = 0.36067376022224085f;   // log2(e)/4  (scale 1/sqrt(DK) folded)
    float rs[4] = {0.f, 0.f, 0.f, 0.f};
#pragma unroll 1
    for (int it = 0; it < 16; it++) {
        const int j = half * 512 + it * 32 + lane;
        const double2* krow = (const double2*)&kv[j * 20];
        ull kp[8];
#pragma unroll
        for (int c = 0; c < 4; c++) {
            double2 t = krow[c];
            kp[2 * c]     = d2ll(t.x);
            kp[2 * c + 1] = d2ll(t.y);
        }
        const float m = msk[j];
#pragma unroll
        for (int r = 0; r < 4; r++) {
            ull s2 = 0ULL;
#pragma unroll
            for (int c = 0; c < 8; c++) s2 = fma2(qp[r][c], kp[c], s2);
            float slo, shi;
            unpack2(s2, slo, shi);
            float e = fast_exp((slo + shi) * C_L2E4) * m;
            sc[(rg + r) * 1024 + j] = e;
            rs[r] += e;
        }
    }
    // row-sum: reduce across lanes, then across the two column halves
#pragma unroll
    for (int o = 16; o > 0; o >>= 1) {
#pragma unroll
        for (int r = 0; r < 4; r++)
            rs[r] += __shfl_xor_sync(0xffffffffu, rs[r], o);
    }
    if (lane == 0) {
#pragma unroll
        for (int r = 0; r < 4; r++) rsp[w * 4 + r] = rs[r];
    }
    __syncthreads();
    if (tid < 32) rsum[tid] = 1.0f / (rsp[tid] + rsp[tid + 32] + 1e-8f);
    __syncthreads();

    // --- stage V over kv (K no longer needed) ---
    {
        const float* vbase = g_v + (size_t)b * NS * ND + h * NDK;
#pragma unroll
        for (int i = 0; i < 8; i++) {
            int idx = tid + i * 512;
            int j = idx >> 2, c = idx & 3;
            float4 t = *(const float4*)(vbase + (size_t)j * ND + c * 4);
            *(float4*)&kv[j * 20 + c * 4] = t;
        }
    }
    __syncthreads();

    // --- Phase 3: context = sc @ v (dual-fp32), attn_w streaming store folded in ---
    float inv[4];
#pragma unroll
    for (int r = 0; r < 4; r++) inv[r] = rsum[rg + r];

    float* aw = attnw + ((size_t)(b * NH + h) * NS + q0) * NS;

    ull accp[4][8];
#pragma unroll
    for (int r = 0; r < 4; r++)
#pragma unroll
        for (int c = 0; c < 8; c++) accp[r][c] = 0ULL;

#pragma unroll 1
    for (int it = 0; it < 16; it++) {
        const int j = half * 512 + it * 32 + lane;
        const double2* vrow = (const double2*)&kv[j * 20];
        ull vp[8];
#pragma unroll
        for (int c = 0; c < 4; c++) {
            double2 t = vrow[c];
            vp[2 * c]     = d2ll(t.x);
            vp[2 * c + 1] = d2ll(t.y);
        }
#pragma unroll
        for (int r = 0; r < 4; r++) {
            float e = sc[(rg + r) * 1024 + j];
            __stcs(aw + (size_t)(rg + r) * NS + j, e * inv[r]);  // streaming: bypass L2 residency
            ull e2 = pack2(e, e);
#pragma unroll
            for (int c = 0; c < 8; c++)
                accp[r][c] = fma2(e2, vp[c], accp[r][c]);
        }
    }

    // lane reduction on packed accumulators (each lane covered disjoint j)
#pragma unroll
    for (int o = 16; o > 0; o >>= 1)
#pragma unroll
        for (int r = 0; r < 4; r++)
#pragma unroll
            for (int c = 0; c < 8; c++)
                accp[r][c] = add2(accp[r][c], __shfl_xor_sync(0xffffffffu, accp[r][c], o));

    if (lane == 0) {
#pragma unroll
        for (int r = 0; r < 4; r++)
#pragma unroll
            for (int c = 0; c < 8; c++) {
                float lo, hi;
                unpack2(accp[r][c], lo, hi);
                cpart[w * 64 + r * 16 + 2 * c]     = lo;
                cpart[w * 64 + r * 16 + 2 * c + 1] = hi;
            }
    }
    __syncthreads();

    // combine the two column-half partials, normalize, write output
    {
        int r = tid >> 4, d = tid & 15;
        int wg = r >> 2, rr = r & 3;
        float v = cpart[wg * 64 + rr * 16 + d] + cpart[(wg + 8) * 64 + rr * 16 + d];
        v *= rsum[r];
        outg[(size_t)(b * NS + q0 + r) * ND + h * NDK + d] = v;
    }
}

// ---------------------------------------------------------------------------
extern "C" void kernel_launch(void* const* d_in, const int* in_sizes, int n_in,
                              void* d_out, int out_size)
{
    const float* Qin  = (const float*)d_in[0];
    const float* Kin  = (const float*)d_in[1];
    const float* Vin  = (const float*)d_in[2];
    const int*   mask = (const int*)d_in[3];
    const float* Wq   = (const float*)d_in[4];
    const float* bq   = (const float*)d_in[5];
    const float* Wk   = (const float*)d_in[6];
    const float* Wv   = (const float*)d_in[7];
    const float* bv   = (const float*)d_in[8];

    float* out   = (float*)d_out;
    float* attnw = out + (size_t)NB * NS * ND;

    dim3 pg(2, 128, 3);
    proj_kernel<<<pg, 256>>>(Qin, Kin, Vin, Wq, bq, Wk, Wv, bv);

    cudaFuncSetAttribute(attn_kernel, cudaFuncAttributeMaxDynamicSharedMemorySize,
                         ATTN_SMEM_BYTES);
    dim3 ag(NS / 32, NH, NB);
    attn_kernel<<<ag, 512, ATTN_SMEM_BYTES>>>(mask, out, attnw);
}

// round 5
// speedup vs baseline: 1.4713x; 1.0007x over previous
#include <cuda_runtime.h>

// Problem constants: B=16, S=1024, D=256, H=16, DK=16
#define NB 16
#define NS 1024
#define ND 256
#define NH 16
#define NDK 16

// Scratch for projected q,k,v: [B, S, 256] row-major (head h occupies cols h*16..h*16+15)
__device__ float g_q[NB * NS * ND];
__device__ float g_k[NB * NS * ND];
__device__ float g_v[NB * NS * ND];

// ---------------------------------------------------------------------------
// Packed dual-fp32 helpers (Blackwell f32x2).
// ---------------------------------------------------------------------------
typedef unsigned long long ull;

static __device__ __forceinline__ ull pack2(float lo, float hi) {
    ull r;
    asm("mov.b64 %0, {%1, %2};" : "=l"(r) : "f"(lo), "f"(hi));
    return r;
}
static __device__ __forceinline__ void unpack2(ull p, float& lo, float& hi) {
    asm("mov.b64 {%0, %1}, %2;" : "=f"(lo), "=f"(hi) : "l"(p));
}
static __device__ __forceinline__ ull fma2(ull a, ull b, ull c) {
    ull d;
    asm("fma.rn.f32x2 %0, %1, %2, %3;" : "=l"(d) : "l"(a), "l"(b), "l"(c));
    return d;
}
static __device__ __forceinline__ ull add2(ull a, ull b) {
    ull d;
    asm("add.rn.f32x2 %0, %1, %2;" : "=l"(d) : "l"(a), "l"(b));
    return d;
}
static __device__ __forceinline__ ull d2ll(double d) {
    return __double_as_longlong(d);
}

// Fast exp on the fma/alu pipes (no MUFU). Input is already x*log2(e).
// Magic-number round + deg-5 poly for 2^f + exponent injection. rel err ~2e-6.
static __device__ __forceinline__ float fast_exp(float t) {
    float mm = t + 12582912.0f;             // round-to-nearest (magic 2^23+2^22)
    int   ik = __float_as_int(mm);
    float n  = mm - 12582912.0f;
    float f  = t - n;                        // f in [-0.5, 0.5]
    float p  =             1.33335581464e-3f;
    p = fmaf(p, f, 9.61812910763e-3f);
    p = fmaf(p, f, 5.55041086648e-2f);
    p = fmaf(p, f, 2.40226506959e-1f);
    p = fmaf(p, f, 6.93147180560e-1f);
    p = fmaf(p, f, 1.0f);
    return __int_as_float(__float_as_int(p) + ((ik - 0x4B400000) << 23));
}

// ---------------------------------------------------------------------------
// Projection GEMM: C[16384,256] = X[16384,256] @ W[256,256] (+bias)
// ---------------------------------------------------------------------------
__global__ __launch_bounds__(256, 2) void proj_kernel(
    const float* __restrict__ Qin, const float* __restrict__ Kin, const float* __restrict__ Vin,
    const float* __restrict__ Wq, const float* __restrict__ bq,
    const float* __restrict__ Wk, const float* __restrict__ Wv, const float* __restrict__ bv)
{
    __shared__ float As[128][17];
    __shared__ float Bs[16][128];

    const int z = blockIdx.z;
    const float* X    = (z == 0) ? Qin : ((z == 1) ? Kin : Vin);
    const float* W    = (z == 0) ? Wq  : ((z == 1) ? Wk  : Wv);
    const float* bias = (z == 0) ? bq  : ((z == 2) ? bv  : (const float*)0);
    float* C          = (z == 0) ? g_q : ((z == 1) ? g_k : g_v);

    const int m0 = blockIdx.y * 128;
    const int n0 = blockIdx.x * 128;
    const int tid = threadIdx.x;
    const int tx = tid & 15;
    const int ty = tid >> 4;

    ull accp[8][4];
#pragma unroll
    for (int i = 0; i < 8; i++)
#pragma unroll
        for (int j = 0; j < 4; j++) accp[i][j] = 0ULL;

    for (int kk = 0; kk < 256; kk += 16) {
#pragma unroll
        for (int i = 0; i < 8; i++) {
            int r = (tid >> 4) + i * 16;
            int c = tid & 15;
            As[r][c] = X[(size_t)(m0 + r) * 256 + kk + c];
        }
#pragma unroll
        for (int i = 0; i < 8; i++) {
            int kr = (tid >> 7) + i * 2;
            int n  = tid & 127;
            Bs[kr][n] = W[(size_t)(kk + kr) * 256 + n0 + n];
        }
        __syncthreads();

#pragma unroll
        for (int k = 0; k < 16; k++) {
            const double2* brow = (const double2*)&Bs[k][tx * 8];
            double2 b0 = brow[0], b1 = brow[1];
            ull bp[4] = { d2ll(b0.x), d2ll(b0.y), d2ll(b1.x), d2ll(b1.y) };
#pragma unroll
            for (int i = 0; i < 8; i++) {
                float a = As[ty * 8 + i][k];
                ull a2 = pack2(a, a);
#pragma unroll
                for (int j = 0; j < 4; j++)
                    accp[i][j] = fma2(a2, bp[j], accp[i][j]);
            }
        }
        __syncthreads();
    }

    float bj[8];
#pragma unroll
    for (int j = 0; j < 8; j++)
        bj[j] = bias ? bias[n0 + tx * 8 + j] : 0.f;

#pragma unroll
    for (int i = 0; i < 8; i++) {
        int m = m0 + ty * 8 + i;
        float v[8];
#pragma unroll
        for (int j = 0; j < 4; j++) unpack2(accp[i][j], v[2 * j], v[2 * j + 1]);
        float4 o0, o1;
        o0.x = v[0] + bj[0]; o0.y = v[1] + bj[1];
        o0.z = v[2] + bj[2]; o0.w = v[3] + bj[3];
        o1.x = v[4] + bj[4]; o1.y = v[5] + bj[5];
        o1.z = v[6] + bj[6]; o1.w = v[7] + bj[7];
        *(float4*)&C[(size_t)m * 256 + n0 + tx * 8]     = o0;
        *(float4*)&C[(size_t)m * 256 + n0 + tx * 8 + 4] = o1;
    }
}

// ---------------------------------------------------------------------------
// Fused attention: one block per (b, h, 32-query tile). 512 threads (16 warps).
// ROUND-2 STRUCTURE (known 127-reg, no spills). Warp w: rows rg=(w&7)*4,
// column half w>>3. Only deltas vs round 2: fast_exp (no MUFU) and __stcs
// streaming stores for attn_w.
// ---------------------------------------------------------------------------
#define SC_OFF    0         // 32768 floats
#define KV_OFF    32768     // 20480
#define QS_OFF    53248     // 512
#define MSK_OFF   53760     // 1024
#define RSUM_OFF  54784     // 32
#define RSP_OFF   54816     // 64
#define CPART_OFF 54880     // 1024
#define ATTN_SMEM_FLOATS 55904
#define ATTN_SMEM_BYTES (ATTN_SMEM_FLOATS * 4)

__global__ __launch_bounds__(512, 1) void attn_kernel(
    const int* __restrict__ maskg, float* __restrict__ outg, float* __restrict__ attnw)
{
    extern __shared__ float sm[];
    float* sc    = sm + SC_OFF;
    float* kv    = sm + KV_OFF;
    float* qs    = sm + QS_OFF;
    float* msk   = sm + MSK_OFF;
    float* rsum  = sm + RSUM_OFF;
    float* rsp   = sm + RSP_OFF;
    float* cpart = sm + CPART_OFF;

    const int qt = blockIdx.x, h = blockIdx.y, b = blockIdx.z;
    const int tid  = threadIdx.x;
    const int lane = tid & 31;
    const int w    = tid >> 5;        // 0..15
    const int rg   = (w & 7) * 4;     // row group (4 rows)
    const int half = w >> 3;          // column half
    const int q0   = qt * 32;

    // --- stage q tile (32x16), mask (1024), K head tile (1024x16) ---
    {
        int r = tid >> 4, d = tid & 15;
        qs[tid] = g_q[(size_t)(b * NS + q0 + r) * ND + h * NDK + d];
    }
    msk[tid]       = (float)maskg[b * NS + tid];
    msk[tid + 512] = (float)maskg[b * NS + tid + 512];
    {
        const float* kbase = g_k + (size_t)b * NS * ND + h * NDK;
#pragma unroll
        for (int i = 0; i < 8; i++) {
            int idx = tid + i * 512;
            int j = idx >> 2, c = idx & 3;
            float4 t = *(const float4*)(kbase + (size_t)j * ND + c * 4);
            *(float4*)&kv[j * 20 + c * 4] = t;
        }
    }
    __syncthreads();

    // q rows -> packed register pairs over d: qp[r][c] = (q[2c], q[2c+1])
    ull qp[4][8];
#pragma unroll
    for (int r = 0; r < 4; r++) {
        const double2* qrow = (const double2*)&qs[(rg + r) * 16];
#pragma unroll
        for (int c = 0; c < 4; c++) {
            double2 t = qrow[c];
            qp[r][2 * c]     = d2ll(t.x);
            qp[r][2 * c + 1] = d2ll(t.y);
        }
    }

    // --- Phase 1: scores (dual-fp32 dot, fast_exp on fma/alu pipes) ---
    const float C_L2E4 = 0.36067376022224085f;   // log2(e)/4  (scale 1/sqrt(DK) folded)
    float rs[4] = {0.f, 0.f, 0.f, 0.f};
#pragma unroll 1
    for (int it = 0; it < 16; it++) {
        const int j = half * 512 + it * 32 + lane;
        const double2* krow = (const double2*)&kv[j * 20];
        ull kp[8];
#pragma unroll
        for (int c = 0; c < 4; c++) {
            double2 t = krow[c];
            kp[2 * c]     = d2ll(t.x);
            kp[2 * c + 1] = d2ll(t.y);
        }
        const float m = msk[j];
#pragma unroll
        for (int r = 0; r < 4; r++) {
            ull s2 = 0ULL;
#pragma unroll
            for (int c = 0; c < 8; c++) s2 = fma2(qp[r][c], kp[c], s2);
            float slo, shi;
            unpack2(s2, slo, shi);
            float e = fast_exp((slo + shi) * C_L2E4) * m;
            sc[(rg + r) * 1024 + j] = e;
            rs[r] += e;
        }
    }
    // row-sum: reduce across lanes, then across the two column halves
#pragma unroll
    for (int o = 16; o > 0; o >>= 1) {
#pragma unroll
        for (int r = 0; r < 4; r++)
            rs[r] += __shfl_xor_sync(0xffffffffu, rs[r], o);
    }
    if (lane == 0) {
#pragma unroll
        for (int r = 0; r < 4; r++) rsp[w * 4 + r] = rs[r];
    }
    __syncthreads();
    if (tid < 32) rsum[tid] = 1.0f / (rsp[tid] + rsp[tid + 32] + 1e-8f);
    __syncthreads();

    // --- stage V over kv (K no longer needed) ---
    {
        const float* vbase = g_v + (size_t)b * NS * ND + h * NDK;
#pragma unroll
        for (int i = 0; i < 8; i++) {
            int idx = tid + i * 512;
            int j = idx >> 2, c = idx & 3;
            float4 t = *(const float4*)(vbase + (size_t)j * ND + c * 4);
            *(float4*)&kv[j * 20 + c * 4] = t;
        }
    }
    __syncthreads();

    // --- Phase 3: context = sc @ v (dual-fp32), attn_w streaming store folded in ---
    float inv[4];
#pragma unroll
    for (int r = 0; r < 4; r++) inv[r] = rsum[rg + r];

    float* aw = attnw + ((size_t)(b * NH + h) * NS + q0) * NS;

    ull accp[4][8];
#pragma unroll
    for (int r = 0; r < 4; r++)
#pragma unroll
        for (int c = 0; c < 8; c++) accp[r][c] = 0ULL;

#pragma unroll 1
    for (int it = 0; it < 16; it++) {
        const int j = half * 512 + it * 32 + lane;
        const double2* vrow = (const double2*)&kv[j * 20];
        ull vp[8];
#pragma unroll
        for (int c = 0; c < 4; c++) {
            double2 t = vrow[c];
            vp[2 * c]     = d2ll(t.x);
            vp[2 * c + 1] = d2ll(t.y);
        }
#pragma unroll
        for (int r = 0; r < 4; r++) {
            float e = sc[(rg + r) * 1024 + j];
            __stcs(aw + (size_t)(rg + r) * NS + j, e * inv[r]);  // streaming: bypass L2 residency
            ull e2 = pack2(e, e);
#pragma unroll
            for (int c = 0; c < 8; c++)
                accp[r][c] = fma2(e2, vp[c], accp[r][c]);
        }
    }

    // lane reduction on packed accumulators (each lane covered disjoint j)
#pragma unroll
    for (int o = 16; o > 0; o >>= 1)
#pragma unroll
        for (int r = 0; r < 4; r++)
#pragma unroll
            for (int c = 0; c < 8; c++)
                accp[r][c] = add2(accp[r][c], __shfl_xor_sync(0xffffffffu, accp[r][c], o));

    if (lane == 0) {
#pragma unroll
        for (int r = 0; r < 4; r++)
#pragma unroll
            for (int c = 0; c < 8; c++) {
                float lo, hi;
                unpack2(accp[r][c], lo, hi);
                cpart[w * 64 + r * 16 + 2 * c]     = lo;
                cpart[w * 64 + r * 16 + 2 * c + 1] = hi;
            }
    }
    __syncthreads();

    // combine the two column-half partials, normalize, write output
    {
        int r = tid >> 4, d = tid & 15;
        int wg = r >> 2, rr = r & 3;
        float v = cpart[wg * 64 + rr * 16 + d] + cpart[(wg + 8) * 64 + rr * 16 + d];
        v *= rsum[r];
        outg[(size_t)(b * NS + q0 + r) * ND + h * NDK + d] = v;
    }
}

// ---------------------------------------------------------------------------
extern "C" void kernel_launch(void* const* d_in, const int* in_sizes, int n_in,
                              void* d_out, int out_size)
{
    const float* Qin  = (const float*)d_in[0];
    const float* Kin  = (const float*)d_in[1];
    const float* Vin  = (const float*)d_in[2];
    const int*   mask = (const int*)d_in[3];
    const float* Wq   = (const float*)d_in[4];
    const float* bq   = (const float*)d_in[5];
    const float* Wk   = (const float*)d_in[6];
    const float* Wv   = (const float*)d_in[7];
    const float* bv   = (const float*)d_in[8];

    float* out   = (float*)d_out;
    float* attnw = out + (size_t)NB * NS * ND;

    dim3 pg(2, 128, 3);
    proj_kernel<<<pg, 256>>>(Qin, Kin, Vin, Wq, bq, Wk, Wv, bv);

    cudaFuncSetAttribute(attn_kernel, cudaFuncAttributeMaxDynamicSharedMemorySize,
                         ATTN_SMEM_BYTES);
    dim3 ag(NS / 32, NH, NB);
    attn_kernel<<<ag, 512, ATTN_SMEM_BYTES>>>(mask, out, attnw);
}